// round 11
// baseline (speedup 1.0000x reference)
#include <cuda_runtime.h>

// ForwardKinematicsLayer: SMPL 24-joint FK, B=262144 bodies.
// Inputs: local_rots [B,24,3,3] f32, root_pos [B,3] f32, offsets [24,3] f32
// Output: concat( global_pos [B,24,3], global_rots [B,24,3,3] ) f32
//
// Block = 256 threads staging, 48 bodies computing. All global traffic is
// coalesced scalar ld/st through a TRANSPOSED smem tile [element_row][body]
// with row stride 49 floats (49*lane mod 32 has gcd(17,32)=1 -> conflict-free
// staging; compute accesses are lane-consecutive). Compute is a fully-
// unrolled register FK chain (one thread per body); global rots overwrite
// the consumed local rots in smem in place.
//
// R8 change: NB 64->48 (smem 75.7->57.0 KB) + __launch_bounds__(256,4)
// -> 4 blocks/SM, 32 warps/SM (was 3 blocks / 24 warps), RF exactly full
// (4*256*64 = 65536 regs). R8 ncu: DRAM=47%, occ=36% -> still concurrency-
// limited; finer 4-block phase staggering covers compute/barrier windows.

#define NJ 24
#define NB 48                 // bodies per block
#define NT 256                // threads per block
#define SROW (NB + 1)         // 49
// rows: [0..215] local->global rots, [216..287] out pos, [288..290] root pos
#define SROWS 291
#define SMEM_BYTES (SROWS * SROW * 4)   // 57,036 B -> 4 blocks/SM (228,144 B < 228 KB carveout)

extern __shared__ float sm[];

__global__ __launch_bounds__(NT, 4)
void fk_kernel(const float* __restrict__ lr,
               const float* __restrict__ root,
               const float* __restrict__ off,
               float* __restrict__ out,
               int B)
{
    const int t  = threadIdx.x;
    const int b0 = blockIdx.x * NB;
    const int nb = min(NB, B - b0);
    const bool full = (nb == NB);

    // ---------- Phase 1: coalesced stage-in (transposed) ----------
    {
        const float* rsrc = root + (size_t)b0 * 3;
        if (t < NB * 3) {                      // 144 < NT, single shot
            int body = t / 3;
            int c    = t - body * 3;
            if (full || body < nb)
                sm[(288 + c) * SROW + body] = rsrc[t];
        }

        const float* src = lr + (size_t)b0 * (NJ * 9);
        if (full) {
            #pragma unroll 6
            for (int idx = t; idx < NB * (NJ * 9); idx += NT) {  // ~40 iters
                int body = idx / 216;
                int c    = idx - body * 216;
                sm[c * SROW + body] = src[idx];  // LDG coalesced, STS stride 49
            }
        } else {
            const int total = nb * (NJ * 9);
            #pragma unroll 6
            for (int idx = t; idx < NB * (NJ * 9); idx += NT) {
                if (idx < total) {
                    int body = idx / 216;
                    int c    = idx - body * 216;
                    sm[c * SROW + body] = src[idx];
                }
            }
        }
    }
    __syncthreads();

    // ---------- Phase 2: register FK chain, one thread per body ----------
    if (t < nb) {
        constexpr int PAR[NJ] = {-1, 0, 0, 0, 1, 2, 3, 4, 5, 6, 7, 8,
                                  9, 9, 9, 12, 13, 14, 16, 17, 18, 19, 20, 21};
        float gr[NJ][9];
        float gp[NJ][3];

        #pragma unroll
        for (int i = 0; i < 9; ++i)
            gr[0][i] = sm[i * SROW + t];            // rows 0..8 already = out rot[0]
        #pragma unroll
        for (int i = 0; i < 3; ++i) {
            gp[0][i] = sm[(288 + i) * SROW + t];
            sm[(216 + i) * SROW + t] = gp[0][i];    // out pos[0]
        }

        #pragma unroll
        for (int j = 1; j < NJ; ++j) {
            const int p = PAR[j];

            float l[9];
            #pragma unroll
            for (int i = 0; i < 9; ++i)
                l[i] = sm[(j * 9 + i) * SROW + t];

            const float o0 = __ldg(&off[j * 3 + 0]);
            const float o1 = __ldg(&off[j * 3 + 1]);
            const float o2 = __ldg(&off[j * 3 + 2]);

            #pragma unroll
            for (int i = 0; i < 3; ++i) {
                gp[j][i] = gp[p][i]
                         + gr[p][i * 3 + 0] * o0
                         + gr[p][i * 3 + 1] * o1
                         + gr[p][i * 3 + 2] * o2;
                sm[(216 + j * 3 + i) * SROW + t] = gp[j][i];
            }

            #pragma unroll
            for (int i = 0; i < 3; ++i) {
                const float a0 = gr[p][i * 3 + 0];
                const float a1 = gr[p][i * 3 + 1];
                const float a2 = gr[p][i * 3 + 2];
                #pragma unroll
                for (int k = 0; k < 3; ++k) {
                    const float v = a0 * l[0 + k] + a1 * l[3 + k] + a2 * l[6 + k];
                    gr[j][i * 3 + k] = v;
                    sm[(j * 9 + i * 3 + k) * SROW + t] = v;  // overwrite consumed l[j]
                }
            }
        }
    }
    __syncthreads();

    // ---------- Phase 3: coalesced stage-out ----------
    {
        float* pdst = out + (size_t)b0 * (NJ * 3);
        if (full) {
            #pragma unroll 6
            for (int idx = t; idx < NB * (NJ * 3); idx += NT) {  // ~13 iters
                int body = idx / 72;
                int c    = idx - body * 72;
                pdst[idx] = sm[(216 + c) * SROW + body];
            }
        } else {
            for (int idx = t; idx < nb * (NJ * 3); idx += NT) {
                int body = idx / 72;
                int c    = idx - body * 72;
                pdst[idx] = sm[(216 + c) * SROW + body];
            }
        }

        float* rdst = out + (size_t)B * (NJ * 3) + (size_t)b0 * (NJ * 9);
        if (full) {
            #pragma unroll 6
            for (int idx = t; idx < NB * (NJ * 9); idx += NT) {  // ~40 iters
                int body = idx / 216;
                int c    = idx - body * 216;
                rdst[idx] = sm[c * SROW + body];
            }
        } else {
            const int total = nb * (NJ * 9);
            #pragma unroll 6
            for (int idx = t; idx < NB * (NJ * 9); idx += NT) {
                if (idx < total) {
                    int body = idx / 216;
                    int c    = idx - body * 216;
                    rdst[idx] = sm[c * SROW + body];
                }
            }
        }
    }
}

extern "C" void kernel_launch(void* const* d_in, const int* in_sizes, int n_in,
                              void* d_out, int out_size)
{
    const float* lr   = (const float*)d_in[0];
    const float* root = (const float*)d_in[1];
    const float* off  = (const float*)d_in[2];

    const int B = in_sizes[0] / (NJ * 9);
    float* out = (float*)d_out;

    // Non-stream, idempotent host config (not captured; allowed under the rules).
    cudaFuncSetAttribute(fk_kernel, cudaFuncAttributeMaxDynamicSharedMemorySize,
                         SMEM_BYTES);

    const int blocks = (B + NB - 1) / NB;
    fk_kernel<<<blocks, NT, SMEM_BYTES>>>(lr, root, off, out, B);
}

// round 13
// speedup vs baseline: 1.2432x; 1.2432x over previous
#include <cuda_runtime.h>

// ForwardKinematicsLayer: SMPL 24-joint FK, B=262144 bodies.
// Inputs: local_rots [B,24,3,3] f32, root_pos [B,3] f32, offsets [24,3] f32
// Output: concat( global_pos [B,24,3], global_rots [B,24,3,3] ) f32
//
// R12: full float4 pipeline. smem = [body][word] rows, stride 292 words
// (73 float4; 73 mod 8 == 1 -> all .128 accesses conflict-free). Stage-in/out
// use LDG.128/STS.128 and LDS.128/STG.128. Compute reads each joint via a
// 3xLDS.128 12-float window (compile-time offsets) and writes global rot/pos
// through a register FIFO emitting aligned STS.128 (216 and 72 float streams,
// exact f4 multiples). R11 evidence: DRAM flat at 45% while occ rose 36->48%
// -> limiter is scalar memory-op structure, not concurrency. 4x fewer ops,
// 4x bytes per op.

#define NJ 24
#define NB 48                  // bodies per block
#define NT 256                 // threads per block
#define SW 292                 // words per body row (4*73); f4 stride 73
// row words: [0..215] local->global rots, [216..287] out pos, [288..290] root
#define SMEM_BYTES (NB * SW * 4)   // 56,064 B

extern __shared__ float sm[];

__global__ __launch_bounds__(NT)
void fk_kernel(const float* __restrict__ lr,
               const float* __restrict__ root,
               const float* __restrict__ off,
               float* __restrict__ out,
               int B)
{
    const int t  = threadIdx.x;
    const int b0 = blockIdx.x * NB;
    const int nb = min(NB, B - b0);
    const bool full = (nb == NB);

    float4* sm4 = reinterpret_cast<float4*>(sm);

    // ---------- Phase 1: float4 stage-in ----------
    {
        const float4* src4 = reinterpret_cast<const float4*>(lr + (size_t)b0 * 216);
        if (full) {
            #pragma unroll 4
            for (int idx = t; idx < NB * 54; idx += NT) {      // 2592 f4
                int body = idx / 54;
                int q    = idx - body * 54;
                sm4[body * 73 + q] = src4[idx];
            }
        } else {
            const int total = nb * 54;
            #pragma unroll 4
            for (int idx = t; idx < NB * 54; idx += NT) {
                if (idx < total) {
                    int body = idx / 54;
                    int q    = idx - body * 54;
                    sm4[body * 73 + q] = src4[idx];
                }
            }
        }
        const float* rsrc = root + (size_t)b0 * 3;
        if (t < NB * 3) {                                      // 144 scalar
            int body = t / 3;
            int c    = t - body * 3;
            if (full || body < nb)
                sm[body * SW + 288 + c] = rsrc[t];
        }
    }
    __syncthreads();

    // ---------- Phase 2: register FK chain, one thread per body ----------
    if (t < nb) {
        constexpr int PAR[NJ] = {-1, 0, 0, 0, 1, 2, 3, 4, 5, 6, 7, 8,
                                  9, 9, 9, 12, 13, 14, 16, 17, 18, 19, 20, 21};
        const int tw  = t * 73;          // f4 row base
        float*  smw   = sm + t * SW;     // word row base

        float gr[NJ][9];
        float gp[NJ][3];

        // rot/pos write FIFOs (all counters compile-time after full unroll)
        int rc = 0, pc = 0;
        float re0, re1, re2, re3, pe0, pe1, pe2, pe3;

#define ROT_PUSH(v) do {                                                    \
            const int _p = rc & 3;                                          \
            if (_p == 0) re0 = (v); else if (_p == 1) re1 = (v);            \
            else if (_p == 2) re2 = (v); else re3 = (v);                    \
            if (_p == 3)                                                    \
                *reinterpret_cast<float4*>(smw + (rc - 3)) =                \
                    make_float4(re0, re1, re2, re3);                        \
            rc++;                                                           \
        } while (0)

#define POS_PUSH(v) do {                                                    \
            const int _p = pc & 3;                                          \
            if (_p == 0) pe0 = (v); else if (_p == 1) pe1 = (v);            \
            else if (_p == 2) pe2 = (v); else pe3 = (v);                    \
            if (_p == 3)                                                    \
                *reinterpret_cast<float4*>(smw + 216 + (pc - 3)) =          \
                    make_float4(pe0, pe1, pe2, pe3);                        \
            pc++;                                                           \
        } while (0)

        #pragma unroll
        for (int j = 0; j < NJ; ++j) {
            // 12-float window covering this joint's 9 locals (offsets constant)
            const int q0 = (9 * j) / 4;
            const int r  = (9 * j) & 3;
            float4 w0 = sm4[tw + q0];
            float4 w1 = sm4[tw + q0 + 1];
            float4 w2 = sm4[tw + q0 + 2];
            float wv[12] = {w0.x, w0.y, w0.z, w0.w,
                            w1.x, w1.y, w1.z, w1.w,
                            w2.x, w2.y, w2.z, w2.w};
            float l[9];
            #pragma unroll
            for (int i = 0; i < 9; ++i) l[i] = wv[r + i];

            if (j == 0) {
                #pragma unroll
                for (int i = 0; i < 9; ++i) gr[0][i] = l[i];
                #pragma unroll
                for (int i = 0; i < 3; ++i) gp[0][i] = smw[288 + i];
            } else {
                const int p = PAR[j];
                const float o0 = __ldg(&off[j * 3 + 0]);
                const float o1 = __ldg(&off[j * 3 + 1]);
                const float o2 = __ldg(&off[j * 3 + 2]);
                #pragma unroll
                for (int i = 0; i < 3; ++i)
                    gp[j][i] = gp[p][i]
                             + gr[p][i * 3 + 0] * o0
                             + gr[p][i * 3 + 1] * o1
                             + gr[p][i * 3 + 2] * o2;
                #pragma unroll
                for (int i = 0; i < 3; ++i) {
                    const float a0 = gr[p][i * 3 + 0];
                    const float a1 = gr[p][i * 3 + 1];
                    const float a2 = gr[p][i * 3 + 2];
                    #pragma unroll
                    for (int k = 0; k < 3; ++k)
                        gr[j][i * 3 + k] = a0 * l[0 + k] + a1 * l[3 + k] + a2 * l[6 + k];
                }
            }

            // stream out (writes trail reads; window prefix overlap is discarded)
            #pragma unroll
            for (int i = 0; i < 9; ++i) ROT_PUSH(gr[j][i]);
            #pragma unroll
            for (int i = 0; i < 3; ++i) POS_PUSH(gp[j][i]);
        }
#undef ROT_PUSH
#undef POS_PUSH
    }
    __syncthreads();

    // ---------- Phase 3: float4 stage-out ----------
    {
        float4* pd4 = reinterpret_cast<float4*>(out + (size_t)b0 * 72);
        float4* rd4 = reinterpret_cast<float4*>(out + (size_t)B * 72 + (size_t)b0 * 216);
        if (full) {
            #pragma unroll 4
            for (int idx = t; idx < NB * 18; idx += NT) {      // 864 f4
                int body = idx / 18;
                int q    = idx - body * 18;
                pd4[idx] = sm4[body * 73 + 54 + q];
            }
            #pragma unroll 4
            for (int idx = t; idx < NB * 54; idx += NT) {      // 2592 f4
                int body = idx / 54;
                int q    = idx - body * 54;
                rd4[idx] = sm4[body * 73 + q];
            }
        } else {
            const int tp = nb * 18, tr = nb * 54;
            #pragma unroll 4
            for (int idx = t; idx < NB * 18; idx += NT) {
                if (idx < tp) {
                    int body = idx / 18;
                    int q    = idx - body * 18;
                    pd4[idx] = sm4[body * 73 + 54 + q];
                }
            }
            #pragma unroll 4
            for (int idx = t; idx < NB * 54; idx += NT) {
                if (idx < tr) {
                    int body = idx / 54;
                    int q    = idx - body * 54;
                    rd4[idx] = sm4[body * 73 + q];
                }
            }
        }
    }
}

extern "C" void kernel_launch(void* const* d_in, const int* in_sizes, int n_in,
                              void* d_out, int out_size)
{
    const float* lr   = (const float*)d_in[0];
    const float* root = (const float*)d_in[1];
    const float* off  = (const float*)d_in[2];

    const int B = in_sizes[0] / (NJ * 9);
    float* out = (float*)d_out;

    cudaFuncSetAttribute(fk_kernel, cudaFuncAttributeMaxDynamicSharedMemorySize,
                         SMEM_BYTES);

    const int blocks = (B + NB - 1) / NB;
    fk_kernel<<<blocks, NT, SMEM_BYTES>>>(lr, root, off, out, B);
}